// round 3
// baseline (speedup 1.0000x reference)
#include <cuda_runtime.h>
#include <math.h>

// Problem constants (fixed shapes from reference: B=4, S=2048, H=1024, O=512)
#define BATCH 4
#define SEQ   2048
#define HID   1024
#define OUT   512

// ---------------------------------------------------------------------------
// Device scratch (static __device__ arrays: allowed; no runtime allocation)
// ---------------------------------------------------------------------------
__device__ float g_scores[(size_t)BATCH * SEQ * SEQ];   // 64 MB
__device__ float g_ct[(size_t)BATCH * SEQ * HID];       // 32 MB
__device__ float g_lam[BATCH * SEQ];                    // 32 KB

// ---------------------------------------------------------------------------
// Kernel 1: lambda gate  lam[row] = sigmoid(ho_row . W_lambda + b_lambda)
// one block (256 thr) per row; each thread handles exactly 4 elements (float4)
// ---------------------------------------------------------------------------
__global__ __launch_bounds__(256)
void k_lambda(const float* __restrict__ ho,
              const float* __restrict__ Wl,
              const float* __restrict__ bl)
{
    const int row = blockIdx.x;                 // 0 .. BATCH*SEQ-1
    const int t   = threadIdx.x;                // 0 .. 255
    const float4 xv = reinterpret_cast<const float4*>(ho + (size_t)row * HID)[t];
    const float4 wv = reinterpret_cast<const float4*>(Wl)[t];
    float s = xv.x * wv.x + xv.y * wv.y + xv.z * wv.z + xv.w * wv.w;

    // warp reduce
    #pragma unroll
    for (int o = 16; o > 0; o >>= 1)
        s += __shfl_xor_sync(0xFFFFFFFFu, s, o);

    __shared__ float sm[8];
    if ((t & 31) == 0) sm[t >> 5] = s;
    __syncthreads();
    if (t == 0) {
        float tot = 0.f;
        #pragma unroll
        for (int i = 0; i < 8; i++) tot += sm[i];
        tot += bl[0];
        g_lam[row] = 1.f / (1.f + expf(-tot));
    }
}

// ---------------------------------------------------------------------------
// Kernel 2: scores = (1/32) * ho · hi^T   (per batch; NT GEMM, M=N=2048, K=1024)
// 128x128 tile, BK=8, 256 threads, 8x8 microtile
// ---------------------------------------------------------------------------
__global__ __launch_bounds__(256, 2)
void k_scores(const float* __restrict__ ho, const float* __restrict__ hi)
{
    const int b = blockIdx.z;
    const float* A = ho + (size_t)b * SEQ * HID;   // [SEQ, HID] row-major
    const float* Bm = hi + (size_t)b * SEQ * HID;  // [SEQ, HID] row-major
    float* C = g_scores + (size_t)b * SEQ * SEQ;   // [SEQ, SEQ]

    __shared__ float As[8][132];   // +4 pad: conflict-free, keeps 16B alignment
    __shared__ float Bs[8][132];

    const int tid = threadIdx.x;
    const int tx = tid & 15, ty = tid >> 4;
    const int m0 = blockIdx.y * 128, n0 = blockIdx.x * 128;
    const int lr = tid >> 1;             // 0..127 (row within tile)
    const int lq = (tid & 1) << 2;       // 0 or 4 (k-quad)

    const float* Aptr = A + (size_t)(m0 + lr) * HID + lq;
    const float* Bptr = Bm + (size_t)(n0 + lr) * HID + lq;

    float acc[8][8];
    #pragma unroll
    for (int i = 0; i < 8; i++)
        #pragma unroll
        for (int j = 0; j < 8; j++) acc[i][j] = 0.f;

    for (int k0 = 0; k0 < HID; k0 += 8) {
        const float4 av = *reinterpret_cast<const float4*>(Aptr + k0);
        const float4 bv = *reinterpret_cast<const float4*>(Bptr + k0);
        As[lq + 0][lr] = av.x; As[lq + 1][lr] = av.y;
        As[lq + 2][lr] = av.z; As[lq + 3][lr] = av.w;
        Bs[lq + 0][lr] = bv.x; Bs[lq + 1][lr] = bv.y;
        Bs[lq + 2][lr] = bv.z; Bs[lq + 3][lr] = bv.w;
        __syncthreads();
        #pragma unroll
        for (int k = 0; k < 8; k++) {
            const float4 a0 = *reinterpret_cast<const float4*>(&As[k][ty << 2]);
            const float4 a1 = *reinterpret_cast<const float4*>(&As[k][64 + (ty << 2)]);
            const float4 b0 = *reinterpret_cast<const float4*>(&Bs[k][tx << 2]);
            const float4 b1 = *reinterpret_cast<const float4*>(&Bs[k][64 + (tx << 2)]);
            const float a[8]  = {a0.x, a0.y, a0.z, a0.w, a1.x, a1.y, a1.z, a1.w};
            const float bb[8] = {b0.x, b0.y, b0.z, b0.w, b1.x, b1.y, b1.z, b1.w};
            #pragma unroll
            for (int i = 0; i < 8; i++)
                #pragma unroll
                for (int j = 0; j < 8; j++) acc[i][j] += a[i] * bb[j];
        }
        __syncthreads();
    }

    const float scale = 0.03125f;   // 1/sqrt(1024)
    #pragma unroll
    for (int i = 0; i < 4; i++) {
        const int r0 = m0 + (ty << 2) + i;
        const int r1 = r0 + 64;
        float4 c;
        c.x = acc[i][0] * scale; c.y = acc[i][1] * scale;
        c.z = acc[i][2] * scale; c.w = acc[i][3] * scale;
        *reinterpret_cast<float4*>(&C[(size_t)r0 * SEQ + n0 + (tx << 2)]) = c;
        c.x = acc[i][4] * scale; c.y = acc[i][5] * scale;
        c.z = acc[i][6] * scale; c.w = acc[i][7] * scale;
        *reinterpret_cast<float4*>(&C[(size_t)r0 * SEQ + n0 + 64 + (tx << 2)]) = c;
        c.x = acc[4 + i][0] * scale; c.y = acc[4 + i][1] * scale;
        c.z = acc[4 + i][2] * scale; c.w = acc[4 + i][3] * scale;
        *reinterpret_cast<float4*>(&C[(size_t)r1 * SEQ + n0 + (tx << 2)]) = c;
        c.x = acc[4 + i][4] * scale; c.y = acc[4 + i][5] * scale;
        c.z = acc[4 + i][6] * scale; c.w = acc[4 + i][7] * scale;
        *reinterpret_cast<float4*>(&C[(size_t)r1 * SEQ + n0 + 64 + (tx << 2)]) = c;
    }
}

// ---------------------------------------------------------------------------
// Kernel 3: row softmax over scores (8192 rows of 2048)
// ---------------------------------------------------------------------------
__global__ __launch_bounds__(256)
void k_softmax()
{
    float* p = g_scores + (size_t)blockIdx.x * SEQ;
    const int t = threadIdx.x;
    float4 v0 = reinterpret_cast<float4*>(p)[t];
    float4 v1 = reinterpret_cast<float4*>(p)[t + 256];

    float m = fmaxf(fmaxf(fmaxf(v0.x, v0.y), fmaxf(v0.z, v0.w)),
                    fmaxf(fmaxf(v1.x, v1.y), fmaxf(v1.z, v1.w)));
    #pragma unroll
    for (int o = 16; o > 0; o >>= 1)
        m = fmaxf(m, __shfl_xor_sync(0xFFFFFFFFu, m, o));

    __shared__ float sm[8];
    if ((t & 31) == 0) sm[t >> 5] = m;
    __syncthreads();
    m = sm[0];
    #pragma unroll
    for (int i = 1; i < 8; i++) m = fmaxf(m, sm[i]);
    __syncthreads();   // before sm reuse

    v0.x = expf(v0.x - m); v0.y = expf(v0.y - m);
    v0.z = expf(v0.z - m); v0.w = expf(v0.w - m);
    v1.x = expf(v1.x - m); v1.y = expf(v1.y - m);
    v1.z = expf(v1.z - m); v1.w = expf(v1.w - m);

    float s = (v0.x + v0.y + v0.z + v0.w) + (v1.x + v1.y + v1.z + v1.w);
    #pragma unroll
    for (int o = 16; o > 0; o >>= 1)
        s += __shfl_xor_sync(0xFFFFFFFFu, s, o);
    if ((t & 31) == 0) sm[t >> 5] = s;
    __syncthreads();
    s = sm[0];
    #pragma unroll
    for (int i = 1; i < 8; i++) s += sm[i];

    const float inv = 1.f / s;
    v0.x *= inv; v0.y *= inv; v0.z *= inv; v0.w *= inv;
    v1.x *= inv; v1.y *= inv; v1.z *= inv; v1.w *= inv;
    reinterpret_cast<float4*>(p)[t]       = v0;
    reinterpret_cast<float4*>(p)[t + 256] = v1;
}

// ---------------------------------------------------------------------------
// Kernel 4: attended = attn · hi, fused gate:
//   ct = lam*ho + (1-lam)*attended     (per batch; NN GEMM M=2048,N=1024,K=2048)
// ---------------------------------------------------------------------------
__global__ __launch_bounds__(256, 2)
void k_attend(const float* __restrict__ hi, const float* __restrict__ ho)
{
    const int b = blockIdx.z;
    const float* A  = g_scores + (size_t)b * SEQ * SEQ;   // attn [SEQ, SEQ]
    const float* Bm = hi + (size_t)b * SEQ * HID;         // [SEQ(K), HID(N)]
    const float* hoB = ho + (size_t)b * SEQ * HID;
    const float* lamB = g_lam + b * SEQ;
    float* C = g_ct + (size_t)b * SEQ * HID;

    __shared__ float As[8][132];
    __shared__ float Bs[8][132];

    const int tid = threadIdx.x;
    const int tx = tid & 15, ty = tid >> 4;
    const int m0 = blockIdx.y * 128, n0 = blockIdx.x * 128;
    const int lr = tid >> 1;
    const int lq = (tid & 1) << 2;
    const int brow = tid >> 5;               // 0..7
    const int bcol = (tid & 31) << 2;        // 0..124

    const float* Aptr = A + (size_t)(m0 + lr) * SEQ + lq;
    const float* Bptr = Bm + (size_t)brow * HID + n0 + bcol;

    float acc[8][8];
    #pragma unroll
    for (int i = 0; i < 8; i++)
        #pragma unroll
        for (int j = 0; j < 8; j++) acc[i][j] = 0.f;

    for (int k0 = 0; k0 < SEQ; k0 += 8) {
        const float4 av = *reinterpret_cast<const float4*>(Aptr + k0);
        const float4 bv = *reinterpret_cast<const float4*>(Bptr + (size_t)k0 * HID);
        As[lq + 0][lr] = av.x; As[lq + 1][lr] = av.y;
        As[lq + 2][lr] = av.z; As[lq + 3][lr] = av.w;
        *reinterpret_cast<float4*>(&Bs[brow][bcol]) = bv;
        __syncthreads();
        #pragma unroll
        for (int k = 0; k < 8; k++) {
            const float4 a0 = *reinterpret_cast<const float4*>(&As[k][ty << 2]);
            const float4 a1 = *reinterpret_cast<const float4*>(&As[k][64 + (ty << 2)]);
            const float4 b0 = *reinterpret_cast<const float4*>(&Bs[k][tx << 2]);
            const float4 b1 = *reinterpret_cast<const float4*>(&Bs[k][64 + (tx << 2)]);
            const float a[8]  = {a0.x, a0.y, a0.z, a0.w, a1.x, a1.y, a1.z, a1.w};
            const float bb[8] = {b0.x, b0.y, b0.z, b0.w, b1.x, b1.y, b1.z, b1.w};
            #pragma unroll
            for (int i = 0; i < 8; i++)
                #pragma unroll
                for (int j = 0; j < 8; j++) acc[i][j] += a[i] * bb[j];
        }
        __syncthreads();
    }

    #pragma unroll
    for (int i = 0; i < 4; i++) {
        const int r0 = m0 + (ty << 2) + i;
        const int r1 = r0 + 64;
        const float l0 = lamB[r0], g0 = 1.f - l0;
        const float l1 = lamB[r1], g1 = 1.f - l1;
        const float4 h00 = *reinterpret_cast<const float4*>(&hoB[(size_t)r0 * HID + n0 + (tx << 2)]);
        const float4 h01 = *reinterpret_cast<const float4*>(&hoB[(size_t)r0 * HID + n0 + 64 + (tx << 2)]);
        const float4 h10 = *reinterpret_cast<const float4*>(&hoB[(size_t)r1 * HID + n0 + (tx << 2)]);
        const float4 h11 = *reinterpret_cast<const float4*>(&hoB[(size_t)r1 * HID + n0 + 64 + (tx << 2)]);
        float4 c;
        c.x = l0 * h00.x + g0 * acc[i][0]; c.y = l0 * h00.y + g0 * acc[i][1];
        c.z = l0 * h00.z + g0 * acc[i][2]; c.w = l0 * h00.w + g0 * acc[i][3];
        *reinterpret_cast<float4*>(&C[(size_t)r0 * HID + n0 + (tx << 2)]) = c;
        c.x = l0 * h01.x + g0 * acc[i][4]; c.y = l0 * h01.y + g0 * acc[i][5];
        c.z = l0 * h01.z + g0 * acc[i][6]; c.w = l0 * h01.w + g0 * acc[i][7];
        *reinterpret_cast<float4*>(&C[(size_t)r0 * HID + n0 + 64 + (tx << 2)]) = c;
        c.x = l1 * h10.x + g1 * acc[4 + i][0]; c.y = l1 * h10.y + g1 * acc[4 + i][1];
        c.z = l1 * h10.z + g1 * acc[4 + i][2]; c.w = l1 * h10.w + g1 * acc[4 + i][3];
        *reinterpret_cast<float4*>(&C[(size_t)r1 * HID + n0 + (tx << 2)]) = c;
        c.x = l1 * h11.x + g1 * acc[4 + i][4]; c.y = l1 * h11.y + g1 * acc[4 + i][5];
        c.z = l1 * h11.z + g1 * acc[4 + i][6]; c.w = l1 * h11.w + g1 * acc[4 + i][7];
        *reinterpret_cast<float4*>(&C[(size_t)r1 * HID + n0 + 64 + (tx << 2)]) = c;
    }
}

// ---------------------------------------------------------------------------
// Kernel 5: out = ct · W_proj + b_proj  (NN GEMM M=8192, N=512, K=1024)
// ---------------------------------------------------------------------------
__global__ __launch_bounds__(256, 2)
void k_proj(const float* __restrict__ Wp, const float* __restrict__ bp,
            float* __restrict__ outp)
{
    const float* A = g_ct;                // [8192, 1024]
    __shared__ float As[8][132];
    __shared__ float Bs[8][132];

    const int tid = threadIdx.x;
    const int tx = tid & 15, ty = tid >> 4;
    const int m0 = blockIdx.y * 128, n0 = blockIdx.x * 128;
    const int lr = tid >> 1;
    const int lq = (tid & 1) << 2;
    const int brow = tid >> 5;
    const int bcol = (tid & 31) << 2;

    const float* Aptr = A + (size_t)(m0 + lr) * HID + lq;
    const float* Bptr = Wp + (size_t)brow * OUT + n0 + bcol;

    float acc[8][8];
    #pragma unroll
    for (int i = 0; i < 8; i++)
        #pragma unroll
        for (int j = 0; j < 8; j++) acc[i][j] = 0.f;

    for (int k0 = 0; k0 < HID; k0 += 8) {
        const float4 av = *reinterpret_cast<const float4*>(Aptr + k0);
        const float4 bv = *reinterpret_cast<const float4*>(Bptr + (size_t)k0 * OUT);
        As[lq + 0][lr] = av.x; As[lq + 1][lr] = av.y;
        As[lq + 2][lr] = av.z; As[lq + 3][lr] = av.w;
        *reinterpret_cast<float4*>(&Bs[brow][bcol]) = bv;
        __syncthreads();
        #pragma unroll
        for (int k = 0; k < 8; k++) {
            const float4 a0 = *reinterpret_cast<const float4*>(&As[k][ty << 2]);
            const float4 a1 = *reinterpret_cast<const float4*>(&As[k][64 + (ty << 2)]);
            const float4 b0 = *reinterpret_cast<const float4*>(&Bs[k][tx << 2]);
            const float4 b1 = *reinterpret_cast<const float4*>(&Bs[k][64 + (tx << 2)]);
            const float a[8]  = {a0.x, a0.y, a0.z, a0.w, a1.x, a1.y, a1.z, a1.w};
            const float bb[8] = {b0.x, b0.y, b0.z, b0.w, b1.x, b1.y, b1.z, b1.w};
            #pragma unroll
            for (int i = 0; i < 8; i++)
                #pragma unroll
                for (int j = 0; j < 8; j++) acc[i][j] += a[i] * bb[j];
        }
        __syncthreads();
    }

    const float4 bp0 = *reinterpret_cast<const float4*>(&bp[n0 + (tx << 2)]);
    const float4 bp1 = *reinterpret_cast<const float4*>(&bp[n0 + 64 + (tx << 2)]);

    #pragma unroll
    for (int i = 0; i < 4; i++) {
        const int r0 = m0 + (ty << 2) + i;
        const int r1 = r0 + 64;
        float4 c;
        c.x = acc[i][0] + bp0.x; c.y = acc[i][1] + bp0.y;
        c.z = acc[i][2] + bp0.z; c.w = acc[i][3] + bp0.w;
        *reinterpret_cast<float4*>(&outp[(size_t)r0 * OUT + n0 + (tx << 2)]) = c;
        c.x = acc[i][4] + bp1.x; c.y = acc[i][5] + bp1.y;
        c.z = acc[i][6] + bp1.z; c.w = acc[i][7] + bp1.w;
        *reinterpret_cast<float4*>(&outp[(size_t)r0 * OUT + n0 + 64 + (tx << 2)]) = c;
        c.x = acc[4 + i][0] + bp0.x; c.y = acc[4 + i][1] + bp0.y;
        c.z = acc[4 + i][2] + bp0.z; c.w = acc[4 + i][3] + bp0.w;
        *reinterpret_cast<float4*>(&outp[(size_t)r1 * OUT + n0 + (tx << 2)]) = c;
        c.x = acc[4 + i][4] + bp1.x; c.y = acc[4 + i][5] + bp1.y;
        c.z = acc[4 + i][6] + bp1.z; c.w = acc[4 + i][7] + bp1.w;
        *reinterpret_cast<float4*>(&outp[(size_t)r1 * OUT + n0 + 64 + (tx << 2)]) = c;
    }
}

// ---------------------------------------------------------------------------
// Launch
// ---------------------------------------------------------------------------
extern "C" void kernel_launch(void* const* d_in, const int* in_sizes, int n_in,
                              void* d_out, int out_size)
{
    const float* ho = (const float*)d_in[0];   // [4, 2048, 1024]
    const float* hi = (const float*)d_in[1];   // [4, 2048, 1024]
    const float* Wl = (const float*)d_in[2];   // [1024, 1]
    const float* bl = (const float*)d_in[3];   // [1]
    const float* Wp = (const float*)d_in[4];   // [1024, 512]
    const float* bp = (const float*)d_in[5];   // [512]
    float* outp = (float*)d_out;               // [4, 2048, 512]

    k_lambda<<<BATCH * SEQ, 256>>>(ho, Wl, bl);

    dim3 g1(SEQ / 128, SEQ / 128, BATCH);      // 16 x 16 x 4
    k_scores<<<g1, 256>>>(ho, hi);

    k_softmax<<<BATCH * SEQ, 256>>>();

    dim3 g2(HID / 128, SEQ / 128, BATCH);      // 8 x 16 x 4
    k_attend<<<g2, 256>>>(hi, ho);

    dim3 g3(OUT / 128, (BATCH * SEQ) / 128, 1);  // 4 x 64
    k_proj<<<g3, 256>>>(Wp, bp, outp);
}

// round 4
// speedup vs baseline: 1.0020x; 1.0020x over previous
#include <cuda_runtime.h>
#include <math.h>

// Problem constants (fixed shapes from reference: B=4, S=2048, H=1024, O=512)
#define BATCH 4
#define SEQ   2048
#define HID   1024
#define OUT   512

// ---------------------------------------------------------------------------
// Device scratch (static __device__ arrays: allowed; no runtime allocation)
// ---------------------------------------------------------------------------
__device__ float g_scores[(size_t)BATCH * SEQ * SEQ];   // 64 MB
__device__ float g_ct[(size_t)BATCH * SEQ * HID];       // 32 MB
__device__ float g_lam[BATCH * SEQ];                    // 32 KB

// ---------------------------------------------------------------------------
// Kernel 1: lambda gate  lam[row] = sigmoid(ho_row . W_lambda + b_lambda)
// one block (256 thr) per row; each thread handles exactly 4 elements (float4)
// ---------------------------------------------------------------------------
__global__ __launch_bounds__(256)
void k_lambda(const float* __restrict__ ho,
              const float* __restrict__ Wl,
              const float* __restrict__ bl)
{
    const int row = blockIdx.x;                 // 0 .. BATCH*SEQ-1
    const int t   = threadIdx.x;                // 0 .. 255
    const float4 xv = reinterpret_cast<const float4*>(ho + (size_t)row * HID)[t];
    const float4 wv = reinterpret_cast<const float4*>(Wl)[t];
    float s = xv.x * wv.x + xv.y * wv.y + xv.z * wv.z + xv.w * wv.w;

    // warp reduce
    #pragma unroll
    for (int o = 16; o > 0; o >>= 1)
        s += __shfl_xor_sync(0xFFFFFFFFu, s, o);

    __shared__ float sm[8];
    if ((t & 31) == 0) sm[t >> 5] = s;
    __syncthreads();
    if (t == 0) {
        float tot = 0.f;
        #pragma unroll
        for (int i = 0; i < 8; i++) tot += sm[i];
        tot += bl[0];
        g_lam[row] = 1.f / (1.f + expf(-tot));
    }
}

// ---------------------------------------------------------------------------
// Kernel 2: scores = (1/32) * ho · hi^T   (per batch; NT GEMM, M=N=2048, K=1024)
// 128x128 tile, BK=8, 256 threads, 8x8 microtile
// ---------------------------------------------------------------------------
__global__ __launch_bounds__(256, 2)
void k_scores(const float* __restrict__ ho, const float* __restrict__ hi)
{
    const int b = blockIdx.z;
    const float* A = ho + (size_t)b * SEQ * HID;   // [SEQ, HID] row-major
    const float* Bm = hi + (size_t)b * SEQ * HID;  // [SEQ, HID] row-major
    float* C = g_scores + (size_t)b * SEQ * SEQ;   // [SEQ, SEQ]

    __shared__ float As[8][132];   // +4 pad: conflict-free, keeps 16B alignment
    __shared__ float Bs[8][132];

    const int tid = threadIdx.x;
    const int tx = tid & 15, ty = tid >> 4;
    const int m0 = blockIdx.y * 128, n0 = blockIdx.x * 128;
    const int lr = tid >> 1;             // 0..127 (row within tile)
    const int lq = (tid & 1) << 2;       // 0 or 4 (k-quad)

    const float* Aptr = A + (size_t)(m0 + lr) * HID + lq;
    const float* Bptr = Bm + (size_t)(n0 + lr) * HID + lq;

    float acc[8][8];
    #pragma unroll
    for (int i = 0; i < 8; i++)
        #pragma unroll
        for (int j = 0; j < 8; j++) acc[i][j] = 0.f;

    for (int k0 = 0; k0 < HID; k0 += 8) {
        const float4 av = *reinterpret_cast<const float4*>(Aptr + k0);
        const float4 bv = *reinterpret_cast<const float4*>(Bptr + k0);
        As[lq + 0][lr] = av.x; As[lq + 1][lr] = av.y;
        As[lq + 2][lr] = av.z; As[lq + 3][lr] = av.w;
        Bs[lq + 0][lr] = bv.x; Bs[lq + 1][lr] = bv.y;
        Bs[lq + 2][lr] = bv.z; Bs[lq + 3][lr] = bv.w;
        __syncthreads();
        #pragma unroll
        for (int k = 0; k < 8; k++) {
            const float4 a0 = *reinterpret_cast<const float4*>(&As[k][ty << 2]);
            const float4 a1 = *reinterpret_cast<const float4*>(&As[k][64 + (ty << 2)]);
            const float4 b0 = *reinterpret_cast<const float4*>(&Bs[k][tx << 2]);
            const float4 b1 = *reinterpret_cast<const float4*>(&Bs[k][64 + (tx << 2)]);
            const float a[8]  = {a0.x, a0.y, a0.z, a0.w, a1.x, a1.y, a1.z, a1.w};
            const float bb[8] = {b0.x, b0.y, b0.z, b0.w, b1.x, b1.y, b1.z, b1.w};
            #pragma unroll
            for (int i = 0; i < 8; i++)
                #pragma unroll
                for (int j = 0; j < 8; j++) acc[i][j] += a[i] * bb[j];
        }
        __syncthreads();
    }

    const float scale = 0.03125f;   // 1/sqrt(1024)
    #pragma unroll
    for (int i = 0; i < 4; i++) {
        const int r0 = m0 + (ty << 2) + i;
        const int r1 = r0 + 64;
        float4 c;
        c.x = acc[i][0] * scale; c.y = acc[i][1] * scale;
        c.z = acc[i][2] * scale; c.w = acc[i][3] * scale;
        *reinterpret_cast<float4*>(&C[(size_t)r0 * SEQ + n0 + (tx << 2)]) = c;
        c.x = acc[i][4] * scale; c.y = acc[i][5] * scale;
        c.z = acc[i][6] * scale; c.w = acc[i][7] * scale;
        *reinterpret_cast<float4*>(&C[(size_t)r0 * SEQ + n0 + 64 + (tx << 2)]) = c;
        c.x = acc[4 + i][0] * scale; c.y = acc[4 + i][1] * scale;
        c.z = acc[4 + i][2] * scale; c.w = acc[4 + i][3] * scale;
        *reinterpret_cast<float4*>(&C[(size_t)r1 * SEQ + n0 + (tx << 2)]) = c;
        c.x = acc[4 + i][4] * scale; c.y = acc[4 + i][5] * scale;
        c.z = acc[4 + i][6] * scale; c.w = acc[4 + i][7] * scale;
        *reinterpret_cast<float4*>(&C[(size_t)r1 * SEQ + n0 + 64 + (tx << 2)]) = c;
    }
}

// ---------------------------------------------------------------------------
// Kernel 3: row softmax over scores (8192 rows of 2048)
// ---------------------------------------------------------------------------
__global__ __launch_bounds__(256)
void k_softmax()
{
    float* p = g_scores + (size_t)blockIdx.x * SEQ;
    const int t = threadIdx.x;
    float4 v0 = reinterpret_cast<float4*>(p)[t];
    float4 v1 = reinterpret_cast<float4*>(p)[t + 256];

    float m = fmaxf(fmaxf(fmaxf(v0.x, v0.y), fmaxf(v0.z, v0.w)),
                    fmaxf(fmaxf(v1.x, v1.y), fmaxf(v1.z, v1.w)));
    #pragma unroll
    for (int o = 16; o > 0; o >>= 1)
        m = fmaxf(m, __shfl_xor_sync(0xFFFFFFFFu, m, o));

    __shared__ float sm[8];
    if ((t & 31) == 0) sm[t >> 5] = m;
    __syncthreads();
    m = sm[0];
    #pragma unroll
    for (int i = 1; i < 8; i++) m = fmaxf(m, sm[i]);
    __syncthreads();   // before sm reuse

    v0.x = expf(v0.x - m); v0.y = expf(v0.y - m);
    v0.z = expf(v0.z - m); v0.w = expf(v0.w - m);
    v1.x = expf(v1.x - m); v1.y = expf(v1.y - m);
    v1.z = expf(v1.z - m); v1.w = expf(v1.w - m);

    float s = (v0.x + v0.y + v0.z + v0.w) + (v1.x + v1.y + v1.z + v1.w);
    #pragma unroll
    for (int o = 16; o > 0; o >>= 1)
        s += __shfl_xor_sync(0xFFFFFFFFu, s, o);
    if ((t & 31) == 0) sm[t >> 5] = s;
    __syncthreads();
    s = sm[0];
    #pragma unroll
    for (int i = 1; i < 8; i++) s += sm[i];

    const float inv = 1.f / s;
    v0.x *= inv; v0.y *= inv; v0.z *= inv; v0.w *= inv;
    v1.x *= inv; v1.y *= inv; v1.z *= inv; v1.w *= inv;
    reinterpret_cast<float4*>(p)[t]       = v0;
    reinterpret_cast<float4*>(p)[t + 256] = v1;
}

// ---------------------------------------------------------------------------
// Kernel 4: attended = attn · hi, fused gate:
//   ct = lam*ho + (1-lam)*attended     (per batch; NN GEMM M=2048,N=1024,K=2048)
// ---------------------------------------------------------------------------
__global__ __launch_bounds__(256, 2)
void k_attend(const float* __restrict__ hi, const float* __restrict__ ho)
{
    const int b = blockIdx.z;
    const float* A  = g_scores + (size_t)b * SEQ * SEQ;   // attn [SEQ, SEQ]
    const float* Bm = hi + (size_t)b * SEQ * HID;         // [SEQ(K), HID(N)]
    const float* hoB = ho + (size_t)b * SEQ * HID;
    const float* lamB = g_lam + b * SEQ;
    float* C = g_ct + (size_t)b * SEQ * HID;

    __shared__ float As[8][132];
    __shared__ float Bs[8][132];

    const int tid = threadIdx.x;
    const int tx = tid & 15, ty = tid >> 4;
    const int m0 = blockIdx.y * 128, n0 = blockIdx.x * 128;
    const int lr = tid >> 1;
    const int lq = (tid & 1) << 2;
    const int brow = tid >> 5;               // 0..7
    const int bcol = (tid & 31) << 2;        // 0..124

    const float* Aptr = A + (size_t)(m0 + lr) * SEQ + lq;
    const float* Bptr = Bm + (size_t)brow * HID + n0 + bcol;

    float acc[8][8];
    #pragma unroll
    for (int i = 0; i < 8; i++)
        #pragma unroll
        for (int j = 0; j < 8; j++) acc[i][j] = 0.f;

    for (int k0 = 0; k0 < SEQ; k0 += 8) {
        const float4 av = *reinterpret_cast<const float4*>(Aptr + k0);
        const float4 bv = *reinterpret_cast<const float4*>(Bptr + (size_t)k0 * HID);
        As[lq + 0][lr] = av.x; As[lq + 1][lr] = av.y;
        As[lq + 2][lr] = av.z; As[lq + 3][lr] = av.w;
        *reinterpret_cast<float4*>(&Bs[brow][bcol]) = bv;
        __syncthreads();
        #pragma unroll
        for (int k = 0; k < 8; k++) {
            const float4 a0 = *reinterpret_cast<const float4*>(&As[k][ty << 2]);
            const float4 a1 = *reinterpret_cast<const float4*>(&As[k][64 + (ty << 2)]);
            const float4 b0 = *reinterpret_cast<const float4*>(&Bs[k][tx << 2]);
            const float4 b1 = *reinterpret_cast<const float4*>(&Bs[k][64 + (tx << 2)]);
            const float a[8]  = {a0.x, a0.y, a0.z, a0.w, a1.x, a1.y, a1.z, a1.w};
            const float bb[8] = {b0.x, b0.y, b0.z, b0.w, b1.x, b1.y, b1.z, b1.w};
            #pragma unroll
            for (int i = 0; i < 8; i++)
                #pragma unroll
                for (int j = 0; j < 8; j++) acc[i][j] += a[i] * bb[j];
        }
        __syncthreads();
    }

    #pragma unroll
    for (int i = 0; i < 4; i++) {
        const int r0 = m0 + (ty << 2) + i;
        const int r1 = r0 + 64;
        const float l0 = lamB[r0], g0 = 1.f - l0;
        const float l1 = lamB[r1], g1 = 1.f - l1;
        const float4 h00 = *reinterpret_cast<const float4*>(&hoB[(size_t)r0 * HID + n0 + (tx << 2)]);
        const float4 h01 = *reinterpret_cast<const float4*>(&hoB[(size_t)r0 * HID + n0 + 64 + (tx << 2)]);
        const float4 h10 = *reinterpret_cast<const float4*>(&hoB[(size_t)r1 * HID + n0 + (tx << 2)]);
        const float4 h11 = *reinterpret_cast<const float4*>(&hoB[(size_t)r1 * HID + n0 + 64 + (tx << 2)]);
        float4 c;
        c.x = l0 * h00.x + g0 * acc[i][0]; c.y = l0 * h00.y + g0 * acc[i][1];
        c.z = l0 * h00.z + g0 * acc[i][2]; c.w = l0 * h00.w + g0 * acc[i][3];
        *reinterpret_cast<float4*>(&C[(size_t)r0 * HID + n0 + (tx << 2)]) = c;
        c.x = l0 * h01.x + g0 * acc[i][4]; c.y = l0 * h01.y + g0 * acc[i][5];
        c.z = l0 * h01.z + g0 * acc[i][6]; c.w = l0 * h01.w + g0 * acc[i][7];
        *reinterpret_cast<float4*>(&C[(size_t)r0 * HID + n0 + 64 + (tx << 2)]) = c;
        c.x = l1 * h10.x + g1 * acc[4 + i][0]; c.y = l1 * h10.y + g1 * acc[4 + i][1];
        c.z = l1 * h10.z + g1 * acc[4 + i][2]; c.w = l1 * h10.w + g1 * acc[4 + i][3];
        *reinterpret_cast<float4*>(&C[(size_t)r1 * HID + n0 + (tx << 2)]) = c;
        c.x = l1 * h11.x + g1 * acc[4 + i][4]; c.y = l1 * h11.y + g1 * acc[4 + i][5];
        c.z = l1 * h11.z + g1 * acc[4 + i][6]; c.w = l1 * h11.w + g1 * acc[4 + i][7];
        *reinterpret_cast<float4*>(&C[(size_t)r1 * HID + n0 + 64 + (tx << 2)]) = c;
    }
}

// ---------------------------------------------------------------------------
// Kernel 5: out = ct · W_proj + b_proj  (NN GEMM M=8192, N=512, K=1024)
// ---------------------------------------------------------------------------
__global__ __launch_bounds__(256, 2)
void k_proj(const float* __restrict__ Wp, const float* __restrict__ bp,
            float* __restrict__ outp)
{
    const float* A = g_ct;                // [8192, 1024]
    __shared__ float As[8][132];
    __shared__ float Bs[8][132];

    const int tid = threadIdx.x;
    const int tx = tid & 15, ty = tid >> 4;
    const int m0 = blockIdx.y * 128, n0 = blockIdx.x * 128;
    const int lr = tid >> 1;
    const int lq = (tid & 1) << 2;
    const int brow = tid >> 5;
    const int bcol = (tid & 31) << 2;

    const float* Aptr = A + (size_t)(m0 + lr) * HID + lq;
    const float* Bptr = Wp + (size_t)brow * OUT + n0 + bcol;

    float acc[8][8];
    #pragma unroll
    for (int i = 0; i < 8; i++)
        #pragma unroll
        for (int j = 0; j < 8; j++) acc[i][j] = 0.f;

    for (int k0 = 0; k0 < HID; k0 += 8) {
        const float4 av = *reinterpret_cast<const float4*>(Aptr + k0);
        const float4 bv = *reinterpret_cast<const float4*>(Bptr + (size_t)k0 * OUT);
        As[lq + 0][lr] = av.x; As[lq + 1][lr] = av.y;
        As[lq + 2][lr] = av.z; As[lq + 3][lr] = av.w;
        *reinterpret_cast<float4*>(&Bs[brow][bcol]) = bv;
        __syncthreads();
        #pragma unroll
        for (int k = 0; k < 8; k++) {
            const float4 a0 = *reinterpret_cast<const float4*>(&As[k][ty << 2]);
            const float4 a1 = *reinterpret_cast<const float4*>(&As[k][64 + (ty << 2)]);
            const float4 b0 = *reinterpret_cast<const float4*>(&Bs[k][tx << 2]);
            const float4 b1 = *reinterpret_cast<const float4*>(&Bs[k][64 + (tx << 2)]);
            const float a[8]  = {a0.x, a0.y, a0.z, a0.w, a1.x, a1.y, a1.z, a1.w};
            const float bb[8] = {b0.x, b0.y, b0.z, b0.w, b1.x, b1.y, b1.z, b1.w};
            #pragma unroll
            for (int i = 0; i < 8; i++)
                #pragma unroll
                for (int j = 0; j < 8; j++) acc[i][j] += a[i] * bb[j];
        }
        __syncthreads();
    }

    const float4 bp0 = *reinterpret_cast<const float4*>(&bp[n0 + (tx << 2)]);
    const float4 bp1 = *reinterpret_cast<const float4*>(&bp[n0 + 64 + (tx << 2)]);

    #pragma unroll
    for (int i = 0; i < 4; i++) {
        const int r0 = m0 + (ty << 2) + i;
        const int r1 = r0 + 64;
        float4 c;
        c.x = acc[i][0] + bp0.x; c.y = acc[i][1] + bp0.y;
        c.z = acc[i][2] + bp0.z; c.w = acc[i][3] + bp0.w;
        *reinterpret_cast<float4*>(&outp[(size_t)r0 * OUT + n0 + (tx << 2)]) = c;
        c.x = acc[i][4] + bp1.x; c.y = acc[i][5] + bp1.y;
        c.z = acc[i][6] + bp1.z; c.w = acc[i][7] + bp1.w;
        *reinterpret_cast<float4*>(&outp[(size_t)r0 * OUT + n0 + 64 + (tx << 2)]) = c;
        c.x = acc[4 + i][0] + bp0.x; c.y = acc[4 + i][1] + bp0.y;
        c.z = acc[4 + i][2] + bp0.z; c.w = acc[4 + i][3] + bp0.w;
        *reinterpret_cast<float4*>(&outp[(size_t)r1 * OUT + n0 + (tx << 2)]) = c;
        c.x = acc[4 + i][4] + bp1.x; c.y = acc[4 + i][5] + bp1.y;
        c.z = acc[4 + i][6] + bp1.z; c.w = acc[4 + i][7] + bp1.w;
        *reinterpret_cast<float4*>(&outp[(size_t)r1 * OUT + n0 + 64 + (tx << 2)]) = c;
    }
}

// ---------------------------------------------------------------------------
// Launch
// ---------------------------------------------------------------------------
extern "C" void kernel_launch(void* const* d_in, const int* in_sizes, int n_in,
                              void* d_out, int out_size)
{
    const float* ho = (const float*)d_in[0];   // [4, 2048, 1024]
    const float* hi = (const float*)d_in[1];   // [4, 2048, 1024]
    const float* Wl = (const float*)d_in[2];   // [1024, 1]
    const float* bl = (const float*)d_in[3];   // [1]
    const float* Wp = (const float*)d_in[4];   // [1024, 512]
    const float* bp = (const float*)d_in[5];   // [512]
    float* outp = (float*)d_out;               // [4, 2048, 512]

    k_lambda<<<BATCH * SEQ, 256>>>(ho, Wl, bl);

    dim3 g1(SEQ / 128, SEQ / 128, BATCH);      // 16 x 16 x 4
    k_scores<<<g1, 256>>>(ho, hi);

    k_softmax<<<BATCH * SEQ, 256>>>();

    dim3 g2(HID / 128, SEQ / 128, BATCH);      // 8 x 16 x 4
    k_attend<<<g2, 256>>>(hi, ho);

    dim3 g3(OUT / 128, (BATCH * SEQ) / 128, 1);  // 4 x 64
    k_proj<<<g3, 256>>>(Wp, bp, outp);
}